// round 2
// baseline (speedup 1.0000x reference)
#include <cuda_runtime.h>

#define TT   512
#define BB   1024
#define OBSN 64
#define HH   256
#define AA   16
#define BM   8
#define NCTA (BB / BM)
#define KLO  120          // rows of W_h^T kept in SMEM; rest streamed from L2
#define SHP  12           // padded row stride for h/obs tiles (bank-conflict-free)

// Scratch (allocation-free rule: __device__ globals)
__device__ float g_WhT[HH * HH];    // W_h transposed: [k][j] = W_h[j][k]
__device__ float g_WiT[OBSN * HH];  // W_in transposed: [k][j] = W_in[j][k]

__global__ void prep_kernel(const float* __restrict__ W_in,
                            const float* __restrict__ W_h) {
    int idx = blockIdx.x * blockDim.x + threadIdx.x;
    if (idx < HH * HH) {
        int k = idx / HH, j = idx % HH;
        g_WhT[idx] = W_h[j * HH + k];
    }
    if (idx < OBSN * HH) {
        int k = idx / HH, j = idx % HH;
        g_WiT[idx] = W_in[j * OBSN + k];
    }
}

typedef unsigned long long u64;

__device__ __forceinline__ u64 pack2(float lo, float hi) {
    u64 u; asm("mov.b64 %0, {%1, %2};" : "=l"(u) : "f"(lo), "f"(hi)); return u;
}
__device__ __forceinline__ void unpack2(u64 v, float& lo, float& hi) {
    asm("mov.b64 {%0, %1}, %2;" : "=f"(lo), "=f"(hi) : "l"(v));
}
// packed dual-FMA: d.lo += a.lo*b.lo ; d.hi += a.hi*b.hi  (FFMA2, PTX-only path)
__device__ __forceinline__ void fma2(u64& d, u64 a, u64 b) {
    asm("fma.rn.f32x2 %0, %1, %2, %0;" : "+l"(d) : "l"(a), "l"(b));
}

__global__ void __launch_bounds__(256, 1) rnn_kernel(
    const float* __restrict__ obs,
    const float* __restrict__ b_h,
    const float* __restrict__ W_out,
    const float* __restrict__ b_out,
    float* __restrict__ out)
{
    extern __shared__ float smem[];
    float* s_h   = smem;                   // [HH][SHP]  h state, layout [j][r] read as [k][r]
    float* s_obs = s_h   + HH * SHP;       // [OBSN][SHP] obs tile transposed
    float* s_Wo  = s_obs + OBSN * SHP;     // [HH][AA]   W_out^T
    float* s_Wi  = s_Wo  + HH * AA;        // [OBSN][HH] W_in^T
    float* s_Wh  = s_Wi  + OBSN * HH;      // [KLO][HH]  low rows of W_h^T

    const int tid = threadIdx.x;
    const int j   = tid;                   // owned hidden unit
    const int b0  = blockIdx.x * BM;

    // ---- one-time init ----
    for (int i = tid; i < HH * SHP; i += 256) s_h[i] = 0.0f;
    for (int i = tid; i < HH * AA; i += 256) {
        int a = i / HH, jj = i % HH;       // coalesced read of W_out[a][jj]
        s_Wo[jj * AA + a] = W_out[i];
    }
    for (int i = tid; i < OBSN * HH; i += 256) s_Wi[i] = g_WiT[i];
    for (int i = tid; i < KLO * HH;  i += 256) s_Wh[i] = g_WhT[i];

    const float bh = b_h[j];
    const int r_o = tid >> 4, a_o = tid & 15;   // output-head mapping (tid < 128)
    float bo = 0.0f, o_reg = 0.0f;
    if (tid < BM * AA) bo = b_out[a_o];

    __syncthreads();

    for (int t = 0; t < TT; ++t) {
        // ---- stage obs[b0..b0+7, t, :] transposed into SMEM ----
        {
            int k = tid & 63;
            int r = tid >> 6;              // 0..3
            s_obs[k * SHP + r]     = obs[((b0 + r)     * TT + t) * OBSN + k];
            s_obs[k * SHP + r + 4] = obs[((b0 + r + 4) * TT + t) * OBSN + k];
        }
        __syncthreads();                   // sync1

        // ---- pre_h[j][r] = b_h[j] + obs·W_in^T + h·W_h^T   (packed f32x2, r-pairs) ----
        u64 a01 = pack2(bh, bh), a23 = a01, a45 = a01, a67 = a01;

        #pragma unroll 8
        for (int k = 0; k < OBSN; ++k) {
            float w = s_Wi[k * HH + j];
            u64 w2 = pack2(w, w);
            const u64* hp = (const u64*)(s_obs + k * SHP);
            fma2(a01, hp[0], w2); fma2(a23, hp[1], w2);
            fma2(a45, hp[2], w2); fma2(a67, hp[3], w2);
        }
        #pragma unroll 8
        for (int k = 0; k < KLO; ++k) {
            float w = s_Wh[k * HH + j];
            u64 w2 = pack2(w, w);
            const u64* hp = (const u64*)(s_h + k * SHP);
            fma2(a01, hp[0], w2); fma2(a23, hp[1], w2);
            fma2(a45, hp[2], w2); fma2(a67, hp[3], w2);
        }
        #pragma unroll 16
        for (int k = KLO; k < HH; ++k) {   // streamed from L2 (shared by all CTAs)
            float w = g_WhT[k * HH + j];
            u64 w2 = pack2(w, w);
            const u64* hp = (const u64*)(s_h + k * SHP);
            fma2(a01, hp[0], w2); fma2(a23, hp[1], w2);
            fma2(a45, hp[2], w2); fma2(a67, hp[3], w2);
        }

        float pre[8];
        unpack2(a01, pre[0], pre[1]); unpack2(a23, pre[2], pre[3]);
        unpack2(a45, pre[4], pre[5]); unpack2(a67, pre[6], pre[7]);

        float hold[8];
        #pragma unroll
        for (int r = 0; r < 8; ++r) hold[r] = s_h[j * SHP + r];

        __syncthreads();                   // sync2: all s_h reads complete

        #pragma unroll
        for (int r = 0; r < 8; ++r) {
            float sg = 1.0f / (1.0f + __expf(-pre[r]));
            s_h[j * SHP + r] = 0.9f * hold[r] + 0.1f * sg;
        }
        __syncthreads();                   // sync3: new h visible

        // ---- output head: pre_o[r][a] = b_out[a] + h_new·W_out^T ----
        if (tid < BM * AA) {
            float acc0 = 0.f, acc1 = 0.f, acc2 = 0.f, acc3 = 0.f;
            #pragma unroll 8
            for (int jj = 0; jj < HH; jj += 4) {
                acc0 += s_h[(jj + 0) * SHP + r_o] * s_Wo[(jj + 0) * AA + a_o];
                acc1 += s_h[(jj + 1) * SHP + r_o] * s_Wo[(jj + 1) * AA + a_o];
                acc2 += s_h[(jj + 2) * SHP + r_o] * s_Wo[(jj + 2) * AA + a_o];
                acc3 += s_h[(jj + 3) * SHP + r_o] * s_Wo[(jj + 3) * AA + a_o];
            }
            float pre_o = bo + ((acc0 + acc1) + (acc2 + acc3));
            float sg = 1.0f / (1.0f + __expf(-pre_o));
            o_reg = 0.9f * o_reg + 0.1f * sg;
            out[((b0 + r_o) * TT + t) * AA + a_o] = o_reg;
        }
        // no barrier needed here: next s_obs write conflicts only with acc-phase
        // readers (done before sync2); next s_h write is after next sync2.
    }

    // ---- final states: layout = [out | h | o] concatenated ----
    #pragma unroll
    for (int r = 0; r < 8; ++r)
        out[BB * TT * AA + (b0 + r) * HH + j] = s_h[j * SHP + r];
    if (tid < BM * AA)
        out[BB * TT * AA + BB * HH + (b0 + r_o) * AA + a_o] = o_reg;
}

extern "C" void kernel_launch(void* const* d_in, const int* in_sizes, int n_in,
                              void* d_out, int out_size) {
    const float* obs   = (const float*)d_in[0];
    const float* W_in  = (const float*)d_in[1];
    const float* W_h   = (const float*)d_in[2];
    const float* b_h   = (const float*)d_in[3];
    const float* W_out = (const float*)d_in[4];
    const float* b_out = (const float*)d_in[5];
    float* out = (float*)d_out;

    prep_kernel<<<(HH * HH + 255) / 256, 256>>>(W_in, W_h);

    size_t shbytes = (size_t)(HH * SHP + OBSN * SHP + HH * AA + OBSN * HH + KLO * HH)
                     * sizeof(float);     // 220,160 B
    cudaFuncSetAttribute(rnn_kernel,
                         cudaFuncAttributeMaxDynamicSharedMemorySize, (int)shbytes);
    rnn_kernel<<<NCTA, 256, shbytes>>>(obs, b_h, W_out, b_out, out);
}